// round 10
// baseline (speedup 1.0000x reference)
#include <cuda_runtime.h>
#include <math.h>

// Problem constants
#define BB 64
#define SS 512
#define PD 300       // feature dim
#define KK 50        // labels
#define KP 64        // padded labels
#define RR 5
#define NROWS (BB*SS)        // 32768
#define BM 64                // rows per K1 block
#define XSS 304              // xs smem row stride
#define CH_ELEMS (150*KP*2)  // 19200 pair-packed chat floats
#define NCH 32               // k3 pooling chunks per batch (16 s each)

// Scratch (device globals; no runtime allocation allowed)
__device__ __align__(16) float g_chat2[CH_ELEMS];    // [pp=150][half=2][tx=16][q=4]
__device__ __align__(16) float g_Gt[BB*KK*SS];       // [b][k][s] cosine scores (transposed)
__device__ __align__(16) float g_m[NROWS];           // conv+relu+max over k
__device__ __align__(16) float g_part[BB*NCH*PD];    // pooling partials

// ---- packed fp32x2 FMA (Blackwell FFMA2 path) ----
__device__ __forceinline__ void fma2(unsigned long long& d,
                                     unsigned long long a,
                                     unsigned long long b) {
    asm("fma.rn.f32x2 %0, %1, %2, %0;" : "+l"(d) : "l"(a), "l"(b));
}
__device__ __forceinline__ float sum2(unsigned long long v) {
    return __uint_as_float((unsigned)v) + __uint_as_float((unsigned)(v >> 32));
}
__device__ __forceinline__ unsigned s2u(const void* p) {
    unsigned a;
    asm("{ .reg .u64 t; cvta.to.shared.u64 t, %1; cvt.u32.u64 %0, t; }"
        : "=r"(a) : "l"(p));
    return a;
}

// ============================================================
// K0: normalize label embeddings C -> packed g_chat2.
// Per pp (512B row): half=0 holds k pairs {4tx,4tx+1}, half=1 {4tx+2,4tx+3},
// thread tx owns contiguous 16B chunks.
// ============================================================
__global__ void k0_chat(const float* __restrict__ C) {
    __shared__ float inv[KP];
    int tid = threadIdx.x;   // 256
    if (tid < KP) {
        float s = 0.f;
        if (tid < KK) {
            const float* row = C + tid * PD;
            for (int p = 0; p < PD; p++) s = fmaf(row[p], row[p], s);
            inv[tid] = 1.f / (sqrtf(s) + 0.001f);
        } else {
            inv[tid] = 0.f;
        }
    }
    __syncthreads();
    const int span = CH_ELEMS / 4;
    const int base = blockIdx.x * span;
    for (int ii = tid; ii < span; ii += 256) {
        int i    = base + ii;
        int pp   = i >> 7;
        int rem  = i & 127;
        int half = rem >> 6;
        int w    = rem & 63;
        int tx   = w >> 2;
        int q    = w & 3;
        int k    = 4 * tx + 2 * half + (q >> 1);
        int e    = q & 1;
        int p    = 2 * pp + e;
        float v = 0.f;
        if (k < KK) v = C[k * PD + p] * inv[k];
        g_chat2[i] = v;
    }
}

// ============================================================
// K1: gathered cosine-score GEMM (round-6 best config).
// Block: 64 rows x 64 k, 256 threads, 4x4 tile/thread.
// chat staged in smem (A LDS are warp-broadcast; B LDS.128 contiguous).
// Stores G TRANSPOSED [b][k][s] for the conv kernel.
// ============================================================
__global__ void __launch_bounds__(256, 1)
k1_scores(const int* __restrict__ idx, const float* __restrict__ emb) {
    extern __shared__ float sm1[];
    float* ch = sm1;                 // CH_ELEMS floats
    float* xs = sm1 + CH_ELEMS;      // BM * XSS floats
    __shared__ float inv[BM];

    const int tid  = threadIdx.x;
    const int lane = tid & 31;
    const int warp = tid >> 5;
    const int row0 = blockIdx.x * BM;

    // stage chat via cp.async (16B)
    {
        const float4* src = (const float4*)g_chat2;
        unsigned dst = s2u(ch);
        for (int i = tid; i < CH_ELEMS / 4; i += 256)
            asm volatile("cp.async.cg.shared.global [%0], [%1], 16;"
                         :: "r"(dst + 16u * (unsigned)i), "l"(src + i));
    }
    // gather x rows via cp.async (batched)
    for (int r = warp; r < BM; r += 8) {
        const float4* src = (const float4*)(emb + (size_t)idx[row0 + r] * PD);
        unsigned dst = s2u(xs + r * XSS);
        #pragma unroll
        for (int i = 0; i < 3; i++) {
            int p4 = lane + 32 * i;
            if (p4 < 75)
                asm volatile("cp.async.cg.shared.global [%0], [%1], 16;"
                             :: "r"(dst + 16u * (unsigned)p4), "l"(src + p4));
        }
    }
    asm volatile("cp.async.commit_group;");
    asm volatile("cp.async.wait_group 0;" ::: "memory");
    __syncthreads();

    // inverse norms (warp per row)
    for (int r = warp; r < BM; r += 8) {
        const float* xr = xs + r * XSS;
        float ss = 0.f;
        #pragma unroll
        for (int i = 0; i < 10; i++) {
            int p = lane + 32 * i;
            if (p < PD) { float v = xr[p]; ss = fmaf(v, v, ss); }
        }
        #pragma unroll
        for (int o = 16; o; o >>= 1) ss += __shfl_xor_sync(0xffffffffu, ss, o);
        if (lane == 0) inv[r] = 1.f / (sqrtf(ss) + 0.001f);
    }
    __syncthreads();

    const int tx = tid & 15;   // k direction (4 k each)
    const int ty = tid >> 4;   // row direction (4 rows each)

    unsigned long long acc[4][4];
    #pragma unroll
    for (int i = 0; i < 4; i++)
        #pragma unroll
        for (int j = 0; j < 4; j++) acc[i][j] = 0ull;

    const float* aBase = xs + (ty * 4) * XSS;
    const float* bBase = ch + tx * 4;   // 16B-stride chunks

    #pragma unroll 2
    for (int pp = 0; pp < 150; pp++) {
        unsigned long long a0 = *(const unsigned long long*)(aBase + 2 * pp);
        unsigned long long a1 = *(const unsigned long long*)(aBase + XSS + 2 * pp);
        unsigned long long a2 = *(const unsigned long long*)(aBase + 2 * XSS + 2 * pp);
        unsigned long long a3 = *(const unsigned long long*)(aBase + 3 * XSS + 2 * pp);
        ulonglong2 B0 = *(const ulonglong2*)(bBase + pp * 128);       // k=4tx,4tx+1
        ulonglong2 B1 = *(const ulonglong2*)(bBase + pp * 128 + 64);  // k=4tx+2,4tx+3
        fma2(acc[0][0], a0, B0.x); fma2(acc[0][1], a0, B0.y);
        fma2(acc[0][2], a0, B1.x); fma2(acc[0][3], a0, B1.y);
        fma2(acc[1][0], a1, B0.x); fma2(acc[1][1], a1, B0.y);
        fma2(acc[1][2], a1, B1.x); fma2(acc[1][3], a1, B1.y);
        fma2(acc[2][0], a2, B0.x); fma2(acc[2][1], a2, B0.y);
        fma2(acc[2][2], a2, B1.x); fma2(acc[2][3], a2, B1.y);
        fma2(acc[3][0], a3, B0.x); fma2(acc[3][1], a3, B0.y);
        fma2(acc[3][2], a3, B1.x); fma2(acc[3][3], a3, B1.y);
    }

    // epilogue: scale, store transposed [b][k][s]
    const int brow  = row0 >> 9;        // batch of this block (BM=64 < SS)
    const int sbase = row0 & (SS - 1);
    #pragma unroll
    for (int i = 0; i < 4; i++) {
        int s = sbase + ty * 4 + i;
        float iv = inv[ty * 4 + i];
        #pragma unroll
        for (int j = 0; j < 4; j++) {
            int k = tx * 4 + j;
            if (k < KK)
                g_Gt[((size_t)brow * KK + k) * SS + s] = sum2(acc[i][j]) * iv;
        }
    }
}

// ============================================================
// K2t: conv(11) + relu + max-over-k from transposed G.
// grid (4 s-tiles, 64 b), 128 threads (one per s).
// smem tile [50 k][139] (138 + pad), rows loaded contiguously.
// ============================================================
#define KST 139
__global__ void __launch_bounds__(128, 2)
k2t_conv(const float* __restrict__ cw, const float* __restrict__ cbp) {
    __shared__ float sm[KK * KST];
    __shared__ float wloc[11];
    __shared__ float cb_s;

    const int cx = blockIdx.x, b = blockIdx.y, tid = threadIdx.x;
    const int s0 = cx * 128;
    if (tid < 11) wloc[tid] = cw[tid];
    if (tid == 16) cb_s = cbp[0];

    // load [50][138] halo tile; zero outside [0,SS)
    const float* Gb = g_Gt + (size_t)b * KK * SS;
    for (int i = tid; i < KK * 138; i += 128) {
        int k = i / 138, r = i - k * 138;
        int sr = s0 - RR + r;
        sm[k * KST + r] = (sr >= 0 && sr < SS) ? Gb[k * SS + sr] : 0.f;
    }
    __syncthreads();

    const float cbv = cb_s;
    float m = 0.f;   // relu >= 0
    for (int k = 0; k < KK; k++) {
        float v = cbv;
        const float* gp = sm + k * KST + tid;
        #pragma unroll
        for (int j = 0; j < 11; j++) v = fmaf(wloc[j], gp[j], v);
        m = fmaxf(m, fmaxf(v, 0.f));
    }
    g_m[b * SS + s0 + tid] = m;
}

// ============================================================
// K3a: fused softmax + pooling partials. grid (32 chunks, 64 b),
// 320 threads. Each block recomputes its batch's softmax stats
// (deterministic, identical order across blocks of the same b),
// then pools 16 s-positions.
// ============================================================
__global__ void __launch_bounds__(320, 4)
k3a_pool(const int* __restrict__ idx, const float* __restrict__ emb) {
    __shared__ float red1[10], red2[10];
    __shared__ float mx_s, sum_s;
    __shared__ float sbeta[16];
    __shared__ int   sidx[16];

    const int cx = blockIdx.x, b = blockIdx.y, tid = threadIdx.x;
    const int lane = tid & 31, warp = tid >> 5;  // 10 warps
    const int s0 = cx * 16;
    const float* mrow = g_m + b * SS;

    // block max over 512
    float ml = -1e30f;
    for (int i = tid; i < SS; i += 320) ml = fmaxf(ml, mrow[i]);
    #pragma unroll
    for (int o = 16; o; o >>= 1) ml = fmaxf(ml, __shfl_xor_sync(0xffffffffu, ml, o));
    if (lane == 0) red1[warp] = ml;
    __syncthreads();
    if (tid < 32) {
        float v = (tid < 10) ? red1[tid] : -1e30f;
        #pragma unroll
        for (int o = 8; o; o >>= 1) v = fmaxf(v, __shfl_xor_sync(0xffffffffu, v, o));
        if (tid == 0) mx_s = v;
    }
    __syncthreads();
    const float mx = mx_s;

    // block sum of exp
    float sl = 0.f;
    for (int i = tid; i < SS; i += 320) sl += expf(mrow[i] - mx);
    #pragma unroll
    for (int o = 16; o; o >>= 1) sl += __shfl_xor_sync(0xffffffffu, sl, o);
    if (lane == 0) red2[warp] = sl;
    __syncthreads();
    if (tid < 32) {
        float v = (tid < 10) ? red2[tid] : 0.f;
        #pragma unroll
        for (int o = 8; o; o >>= 1) v += __shfl_xor_sync(0xffffffffu, v, o);
        if (tid == 0) sum_s = v;
    }
    __syncthreads();

    if (tid < 16) {
        sbeta[tid] = expf(mrow[s0 + tid] - mx) / sum_s;
        sidx[tid]  = idx[b * SS + s0 + tid];
    }
    __syncthreads();

    if (tid < PD) {
        float a[8];
        #pragma unroll
        for (int i = 0; i < 8; i++) a[i] = 0.f;
        #pragma unroll
        for (int s = 0; s < 16; s += 8) {
            #pragma unroll
            for (int i = 0; i < 8; i++)
                a[i] = fmaf(sbeta[s + i],
                            __ldg(emb + (size_t)sidx[s + i] * PD + tid), a[i]);
        }
        float r = ((a[0] + a[1]) + (a[2] + a[3])) + ((a[4] + a[5]) + (a[6] + a[7]));
        g_part[(b * NCH + cx) * PD + tid] = r;
    }
}

// ============================================================
// K3b: combine partials + final GEMV out = pooled @ W2^T + b2.
// ============================================================
__global__ void __launch_bounds__(320, 4)
k3b_out(const float* __restrict__ W2, const float* __restrict__ b2,
        float* __restrict__ out) {
    __shared__ float pooled[PD];
    const int b = blockIdx.x, tid = threadIdx.x;
    if (tid < PD) {
        float s = 0.f;
        #pragma unroll
        for (int c = 0; c < NCH; c++) s += g_part[(b * NCH + c) * PD + tid];
        pooled[tid] = s * (1.0f / (float)SS);
    }
    __syncthreads();

    const int warp = tid >> 5, lane = tid & 31;  // 10 warps x 5 k
    #pragma unroll
    for (int kk = 0; kk < 5; kk++) {
        int k = warp * 5 + kk;
        float d = 0.f;
        for (int p = lane; p < PD; p += 32) d = fmaf(pooled[p], W2[k * PD + p], d);
        #pragma unroll
        for (int o = 16; o; o >>= 1) d += __shfl_xor_sync(0xffffffffu, d, o);
        if (lane == 0) out[b * KK + k] = d + b2[k];
    }
}

// ============================================================
extern "C" void kernel_launch(void* const* d_in, const int* in_sizes, int n_in,
                              void* d_out, int out_size) {
    const int*   idx    = (const int*)d_in[0];
    const float* emb    = (const float*)d_in[1];
    const float* C      = (const float*)d_in[2];
    const float* conv_w = (const float*)d_in[3];
    const float* conv_b = (const float*)d_in[4];
    const float* W2     = (const float*)d_in[5];
    const float* b2     = (const float*)d_in[6];
    float*       out    = (float*)d_out;

    const int sm1 = (CH_ELEMS + BM * XSS) * (int)sizeof(float);   // ~153 KB
    cudaFuncSetAttribute(k1_scores, cudaFuncAttributeMaxDynamicSharedMemorySize, sm1);

    k0_chat<<<4, 256>>>(C);
    k1_scores<<<NROWS / BM, 256, sm1>>>(idx, emb);
    k2t_conv<<<dim3(4, BB), 128>>>(conv_w, conv_b);
    k3a_pool<<<dim3(NCH, BB), 320>>>(idx, emb);
    k3b_out<<<BB, 320>>>(W2, b2, out);
}

// round 12
// speedup vs baseline: 1.1021x; 1.1021x over previous
#include <cuda_runtime.h>
#include <math.h>

// Problem constants
#define BB 64
#define SS 512
#define PD 300       // feature dim
#define KK 50        // labels
#define KP 64        // padded labels
#define RR 5
#define NROWS (BB*SS)        // 32768
#define BM 64                // rows per K1 block
#define XSS 304              // xs smem row stride (16B-aligned rows)
#define CH_ELEMS (150*KP*2)  // 19200 pair-packed chat floats
#define NCH 8                // k3 pooling chunks per batch (measured best)

// Scratch (device globals; no runtime allocation allowed)
__device__ __align__(16) float g_chat2[CH_ELEMS];   // [pp=150][half=2][tx=16][q=4]
__device__ __align__(16) float g_G[NROWS*KK];       // [row][k] cosine scores
__device__ __align__(16) float g_beta[NROWS];       // softmax weights
__device__ __align__(16) float g_part[BB*NCH*PD];   // pooling partials

// ---- packed fp32x2 FMA (Blackwell FFMA2 path) ----
__device__ __forceinline__ void fma2(unsigned long long& d,
                                     unsigned long long a,
                                     unsigned long long b) {
    asm("fma.rn.f32x2 %0, %1, %2, %0;" : "+l"(d) : "l"(a), "l"(b));
}
__device__ __forceinline__ float sum2(unsigned long long v) {
    return __uint_as_float((unsigned)v) + __uint_as_float((unsigned)(v >> 32));
}
__device__ __forceinline__ unsigned s2u(const void* p) {
    unsigned a;
    asm("{ .reg .u64 t; cvta.to.shared.u64 t, %1; cvt.u32.u64 %0, t; }"
        : "=r"(a) : "l"(p));
    return a;
}
union F4U2 { float4 f; unsigned long long u[2]; };

// ============================================================
// K0: normalize label embeddings C -> conflict-free packed g_chat2.
// Per pp (512B row): half=0 holds k pairs {4tx, 4tx+1}, half=1 {4tx+2, 4tx+3};
// thread tx reads its 4 k-pairs as two LDS.128 at tx*16B (conflict-free).
// ============================================================
__global__ void k0_chat(const float* __restrict__ C) {
    __shared__ float inv[KP];
    int tid = threadIdx.x;   // 256
    if (tid < KP) {
        float s = 0.f;
        if (tid < KK) {
            const float* row = C + tid * PD;
            for (int p = 0; p < PD; p++) s = fmaf(row[p], row[p], s);
            inv[tid] = 1.f / (sqrtf(s) + 0.001f);
        } else {
            inv[tid] = 0.f;
        }
    }
    __syncthreads();
    const int span = CH_ELEMS / 4;
    const int base = blockIdx.x * span;
    for (int ii = tid; ii < span; ii += 256) {
        int i    = base + ii;
        int pp   = i >> 7;
        int rem  = i & 127;
        int half = rem >> 6;
        int w    = rem & 63;
        int tx   = w >> 2;
        int q    = w & 3;
        int k    = 4 * tx + 2 * half + (q >> 1);
        int e    = q & 1;
        int p    = 2 * pp + e;
        float v = 0.f;
        if (k < KK) v = C[k * PD + p] * inv[k];
        g_chat2[i] = v;
    }
}

// ============================================================
// K1: gathered cosine-score GEMM (round-6 config + software-pipelined
// mainloop). Block: 64 rows x 64 k, 256 threads, 4x4 tile/thread.
// A + chat in smem. Inner loop: register double-buffer over 2 p-pairs —
// prefetch next 4xLDS.128(A) + 4xLDS.128(B) before the 32-fma2 math
// block, hiding the 29-cyc LDS latency at occ 1 (2 warps/SMSP).
// ============================================================
__global__ void __launch_bounds__(256, 1)
k1_scores(const int* __restrict__ idx, const float* __restrict__ emb) {
    extern __shared__ float sm1[];
    float* ch = sm1;                 // CH_ELEMS floats
    float* xs = sm1 + CH_ELEMS;      // BM * XSS floats
    __shared__ float inv[BM];

    const int tid  = threadIdx.x;
    const int lane = tid & 31;
    const int warp = tid >> 5;
    const int row0 = blockIdx.x * BM;

    // stage chat via cp.async (16B)
    {
        const float4* src = (const float4*)g_chat2;
        unsigned dst = s2u(ch);
        for (int i = tid; i < CH_ELEMS / 4; i += 256)
            asm volatile("cp.async.cg.shared.global [%0], [%1], 16;"
                         :: "r"(dst + 16u * (unsigned)i), "l"(src + i));
    }
    // gather x rows via cp.async (batched)
    for (int r = warp; r < BM; r += 8) {
        const float4* src = (const float4*)(emb + (size_t)idx[row0 + r] * PD);
        unsigned dst = s2u(xs + r * XSS);
        #pragma unroll
        for (int i = 0; i < 3; i++) {
            int p4 = lane + 32 * i;
            if (p4 < 75)
                asm volatile("cp.async.cg.shared.global [%0], [%1], 16;"
                             :: "r"(dst + 16u * (unsigned)p4), "l"(src + p4));
        }
    }
    asm volatile("cp.async.commit_group;");
    asm volatile("cp.async.wait_group 0;" ::: "memory");
    __syncthreads();

    // inverse norms (warp per row)
    for (int r = warp; r < BM; r += 8) {
        const float* xr = xs + r * XSS;
        float ss = 0.f;
        #pragma unroll
        for (int i = 0; i < 10; i++) {
            int p = lane + 32 * i;
            if (p < PD) { float v = xr[p]; ss = fmaf(v, v, ss); }
        }
        #pragma unroll
        for (int o = 16; o; o >>= 1) ss += __shfl_xor_sync(0xffffffffu, ss, o);
        if (lane == 0) inv[r] = 1.f / (sqrtf(ss) + 0.001f);
    }
    __syncthreads();

    const int tx = tid & 15;   // k direction (4 k each)
    const int ty = tid >> 4;   // row direction (4 rows each)

    unsigned long long acc[4][4];
    #pragma unroll
    for (int i = 0; i < 4; i++)
        #pragma unroll
        for (int j = 0; j < 4; j++) acc[i][j] = 0ull;

    const float* aBase = xs + (ty * 4) * XSS;
    const float* bBase = ch + tx * 4;   // 16B-stride chunks, conflict-free

    // ---- software-pipelined mainloop: 2 p-pairs per iteration ----
    F4U2 aC[4], aN[4];
    ulonglong2 bC[4], bN[4];

    // prologue: load pp = 0,1
    #pragma unroll
    for (int i = 0; i < 4; i++)
        aC[i].f = *(const float4*)(aBase + i * XSS);
    bC[0] = *(const ulonglong2*)(bBase);          // pp0 k0,k1
    bC[1] = *(const ulonglong2*)(bBase + 64);     // pp0 k2,k3
    bC[2] = *(const ulonglong2*)(bBase + 128);    // pp1 k0,k1
    bC[3] = *(const ulonglong2*)(bBase + 192);    // pp1 k2,k3

    #pragma unroll 1
    for (int pp = 0; pp < 148; pp += 2) {
        // prefetch pp+2, pp+3
        const float* aP = aBase + 2 * (pp + 2);
        const float* bP = bBase + (pp + 2) * 128;
        #pragma unroll
        for (int i = 0; i < 4; i++)
            aN[i].f = *(const float4*)(aP + i * XSS);
        bN[0] = *(const ulonglong2*)(bP);
        bN[1] = *(const ulonglong2*)(bP + 64);
        bN[2] = *(const ulonglong2*)(bP + 128);
        bN[3] = *(const ulonglong2*)(bP + 192);
        // math block: 32 fma2 on current registers
        #pragma unroll
        for (int i = 0; i < 4; i++) {
            fma2(acc[i][0], aC[i].u[0], bC[0].x);
            fma2(acc[i][1], aC[i].u[0], bC[0].y);
            fma2(acc[i][2], aC[i].u[0], bC[1].x);
            fma2(acc[i][3], aC[i].u[0], bC[1].y);
        }
        #pragma unroll
        for (int i = 0; i < 4; i++) {
            fma2(acc[i][0], aC[i].u[1], bC[2].x);
            fma2(acc[i][1], aC[i].u[1], bC[2].y);
            fma2(acc[i][2], aC[i].u[1], bC[3].x);
            fma2(acc[i][3], aC[i].u[1], bC[3].y);
        }
        // rotate buffers
        #pragma unroll
        for (int i = 0; i < 4; i++) aC[i] = aN[i];
        #pragma unroll
        for (int i = 0; i < 4; i++) bC[i] = bN[i];
    }
    // epilogue: pp = 148,149 (already in current registers)
    #pragma unroll
    for (int i = 0; i < 4; i++) {
        fma2(acc[i][0], aC[i].u[0], bC[0].x);
        fma2(acc[i][1], aC[i].u[0], bC[0].y);
        fma2(acc[i][2], aC[i].u[0], bC[1].x);
        fma2(acc[i][3], aC[i].u[0], bC[1].y);
    }
    #pragma unroll
    for (int i = 0; i < 4; i++) {
        fma2(acc[i][0], aC[i].u[1], bC[2].x);
        fma2(acc[i][1], aC[i].u[1], bC[2].y);
        fma2(acc[i][2], aC[i].u[1], bC[3].x);
        fma2(acc[i][3], aC[i].u[1], bC[3].y);
    }

    // epilogue: scale by 1/(||x||+eps), store k<50
    #pragma unroll
    for (int i = 0; i < 4; i++) {
        int row = row0 + ty * 4 + i;
        float iv = inv[ty * 4 + i];
        float* gout = g_G + (size_t)row * KK;
        #pragma unroll
        for (int j = 0; j < 4; j++) {
            int k = tx * 4 + j;
            if (k < KK) gout[k] = sum2(acc[i][j]) * iv;
        }
    }
}

// ============================================================
// K2: per-batch conv(11) + relu + max-over-k + softmax over s.
// One block per b, 512 threads. Padded smem tile, stride 51.
// ============================================================
#define GST 51
#define GROWS (SS + 2*RR)   // 522

__global__ void __launch_bounds__(512, 1)
k2_attn(const float* __restrict__ cw, const float* __restrict__ cbp) {
    extern __shared__ float Gs[];   // GROWS * GST
    __shared__ float red1[16], red2[16];
    __shared__ float wloc[11];
    __shared__ float sc[3];         // [0]=conv_b, [1]=max, [2]=sum

    const int b = blockIdx.x, tid = threadIdx.x;
    if (tid < 11) wloc[tid] = cw[tid];
    if (tid == 16) sc[0] = cbp[0];

    for (int i = tid; i < RR * GST; i += 512) {
        Gs[i] = 0.f;
        Gs[(SS + RR) * GST + i] = 0.f;
    }
    const float* Gb = g_G + (size_t)b * SS * KK;
    for (int i = tid; i < SS * KK; i += 512) {
        int s = i / KK, k = i - s * KK;
        Gs[(s + RR) * GST + k] = Gb[i];
    }
    __syncthreads();

    const int s = tid;
    const float cbv = sc[0];
    float m = 0.f;   // relu >= 0
    for (int k = 0; k < KK; k++) {
        float v = cbv;
        const float* gp = Gs + s * GST + k;
        #pragma unroll
        for (int j = 0; j < 11; j++) v = fmaf(wloc[j], gp[j * GST], v);
        m = fmaxf(m, fmaxf(v, 0.f));
    }

    const int lane = tid & 31, warp = tid >> 5;
    float mx = m;
    #pragma unroll
    for (int o = 16; o; o >>= 1) mx = fmaxf(mx, __shfl_xor_sync(0xffffffffu, mx, o));
    if (lane == 0) red1[warp] = mx;
    __syncthreads();
    if (warp == 0) {
        float v = (lane < 16) ? red1[lane] : -1e30f;
        #pragma unroll
        for (int o = 8; o; o >>= 1) v = fmaxf(v, __shfl_xor_sync(0xffffffffu, v, o));
        if (lane == 0) sc[1] = v;
    }
    __syncthreads();
    float e = expf(m - sc[1]);
    float sum = e;
    #pragma unroll
    for (int o = 16; o; o >>= 1) sum += __shfl_xor_sync(0xffffffffu, sum, o);
    if (lane == 0) red2[warp] = sum;
    __syncthreads();
    if (warp == 0) {
        float v = (lane < 16) ? red2[lane] : 0.f;
        #pragma unroll
        for (int o = 8; o; o >>= 1) v += __shfl_xor_sync(0xffffffffu, v, o);
        if (lane == 0) sc[2] = v;
    }
    __syncthreads();
    g_beta[b * SS + s] = e / sc[2];
}

// ============================================================
// K3a: pooling partials. grid (8 chunks, 64 b), 320 threads,
// 64 s per block (measured-best config).
// ============================================================
__global__ void __launch_bounds__(320, 1)
k3a_pool(const int* __restrict__ idx, const float* __restrict__ emb) {
    __shared__ float sbeta[64];
    __shared__ int   sidx[64];
    const int cx = blockIdx.x, b = blockIdx.y, tid = threadIdx.x;
    const int s0 = b * SS + cx * 64;
    if (tid < 64) {
        sbeta[tid] = g_beta[s0 + tid];
        sidx[tid]  = idx[s0 + tid];
    }
    __syncthreads();
    if (tid < PD) {
        float a0 = 0.f, a1 = 0.f, a2 = 0.f, a3 = 0.f;
        #pragma unroll 4
        for (int s = 0; s < 64; s += 4) {
            a0 = fmaf(sbeta[s],     emb[(size_t)sidx[s]     * PD + tid], a0);
            a1 = fmaf(sbeta[s + 1], emb[(size_t)sidx[s + 1] * PD + tid], a1);
            a2 = fmaf(sbeta[s + 2], emb[(size_t)sidx[s + 2] * PD + tid], a2);
            a3 = fmaf(sbeta[s + 3], emb[(size_t)sidx[s + 3] * PD + tid], a3);
        }
        g_part[(b * NCH + cx) * PD + tid] = (a0 + a1) + (a2 + a3);
    }
}

// ============================================================
// K3b: combine partials + final GEMV out = pooled @ W2^T + b2.
// ============================================================
__global__ void __launch_bounds__(320, 4)
k3b_out(const float* __restrict__ W2, const float* __restrict__ b2,
        float* __restrict__ out) {
    __shared__ float pooled[PD];
    const int b = blockIdx.x, tid = threadIdx.x;
    if (tid < PD) {
        float s = 0.f;
        #pragma unroll
        for (int c = 0; c < NCH; c++) s += g_part[(b * NCH + c) * PD + tid];
        pooled[tid] = s * (1.0f / (float)SS);
    }
    __syncthreads();

    const int warp = tid >> 5, lane = tid & 31;  // 10 warps x 5 k
    #pragma unroll
    for (int kk = 0; kk < 5; kk++) {
        int k = warp * 5 + kk;
        float d = 0.f;
        for (int p = lane; p < PD; p += 32) d = fmaf(pooled[p], W2[k * PD + p], d);
        #pragma unroll
        for (int o = 16; o; o >>= 1) d += __shfl_xor_sync(0xffffffffu, d, o);
        if (lane == 0) out[b * KK + k] = d + b2[k];
    }
}

// ============================================================
extern "C" void kernel_launch(void* const* d_in, const int* in_sizes, int n_in,
                              void* d_out, int out_size) {
    const int*   idx    = (const int*)d_in[0];
    const float* emb    = (const float*)d_in[1];
    const float* C      = (const float*)d_in[2];
    const float* conv_w = (const float*)d_in[3];
    const float* conv_b = (const float*)d_in[4];
    const float* W2     = (const float*)d_in[5];
    const float* b2     = (const float*)d_in[6];
    float*       out    = (float*)d_out;

    const int sm1 = (CH_ELEMS + BM * XSS) * (int)sizeof(float);   // ~153 KB
    const int sm2 = GROWS * GST * (int)sizeof(float);             // ~106 KB
    cudaFuncSetAttribute(k1_scores, cudaFuncAttributeMaxDynamicSharedMemorySize, sm1);
    cudaFuncSetAttribute(k2_attn,   cudaFuncAttributeMaxDynamicSharedMemorySize, sm2);

    k0_chat<<<4, 256>>>(C);
    k1_scores<<<NROWS / BM, 256, sm1>>>(idx, emb);
    k2_attn<<<BB, 512, sm2>>>(conv_w, conv_b);
    k3a_pool<<<dim3(NCH, BB), 320>>>(idx, emb);
    k3b_out<<<BB, 320>>>(W2, b2, out);
}

// round 13
// speedup vs baseline: 1.1275x; 1.0230x over previous
#include <cuda_runtime.h>
#include <math.h>

// Problem constants
#define BB 64
#define SS 512
#define PD 300       // feature dim
#define KK 50        // labels
#define KP 64        // padded labels
#define RR 5
#define NROWS (BB*SS)        // 32768
#define BM 64                // rows per K1 block
#define XSS 304              // xs smem row stride (1216B rows, 16B multiple)
#define CH_ELEMS (150*KP*2)  // 19200 pair-packed chat floats (76800 B)
#define NCH 8                // k3 pooling chunks per batch (measured best)

#define CH_BYTES (CH_ELEMS*4)          // 76800
#define ROW_BYTES (PD*4)               // 1200 (75 x 16B)
#define TOTAL_TX (CH_BYTES + BM*ROW_BYTES)   // 153600

// Scratch (device globals; no runtime allocation allowed)
__device__ __align__(16) float g_chat2[CH_ELEMS];   // [pp=150][half=2][tx=16][q=4]
__device__ __align__(16) float g_G[NROWS*KK];       // [row][k] cosine scores
__device__ __align__(16) float g_beta[NROWS];       // softmax weights
__device__ __align__(16) float g_part[BB*NCH*PD];   // pooling partials

// ---- packed fp32x2 FMA (Blackwell FFMA2 path) ----
__device__ __forceinline__ void fma2(unsigned long long& d,
                                     unsigned long long a,
                                     unsigned long long b) {
    asm("fma.rn.f32x2 %0, %1, %2, %0;" : "+l"(d) : "l"(a), "l"(b));
}
__device__ __forceinline__ float sum2(unsigned long long v) {
    return __uint_as_float((unsigned)v) + __uint_as_float((unsigned)(v >> 32));
}
__device__ __forceinline__ unsigned s2u(const void* p) {
    unsigned a;
    asm("{ .reg .u64 t; cvta.to.shared.u64 t, %1; cvt.u32.u64 %0, t; }"
        : "=r"(a) : "l"(p));
    return a;
}
__device__ __forceinline__ void bulk_cp(unsigned dst, const void* src,
                                        unsigned bytes, unsigned mbar) {
    asm volatile(
        "cp.async.bulk.shared::cluster.global.mbarrier::complete_tx::bytes "
        "[%0], [%1], %2, [%3];"
        :: "r"(dst), "l"(src), "r"(bytes), "r"(mbar) : "memory");
}
__device__ __forceinline__ void mbar_wait(unsigned addr, unsigned parity) {
    asm volatile(
        "{\n\t.reg .pred P1;\n\t"
        "WAIT_%=: mbarrier.try_wait.parity.acquire.cta.shared::cta.b64 P1, [%0], %1, 0x989680;\n\t"
        "@P1 bra DONE_%=;\n\tbra WAIT_%=;\n\tDONE_%=:\n\t}"
        :: "r"(addr), "r"(parity) : "memory");
}
union F4U2 { float4 f; unsigned long long u[2]; };

// ============================================================
// K0: normalize label embeddings C -> conflict-free packed g_chat2.
// Per pp (512B row): half=0 holds k pairs {4tx, 4tx+1}, half=1 {4tx+2, 4tx+3};
// thread tx reads its 4 k-pairs as two LDS.128 at tx*16B (conflict-free).
// ============================================================
__global__ void k0_chat(const float* __restrict__ C) {
    __shared__ float inv[KP];
    int tid = threadIdx.x;   // 256
    if (tid < KP) {
        float s = 0.f;
        if (tid < KK) {
            const float* row = C + tid * PD;
            for (int p = 0; p < PD; p++) s = fmaf(row[p], row[p], s);
            inv[tid] = 1.f / (sqrtf(s) + 0.001f);
        } else {
            inv[tid] = 0.f;
        }
    }
    __syncthreads();
    const int span = CH_ELEMS / 4;
    const int base = blockIdx.x * span;
    for (int ii = tid; ii < span; ii += 256) {
        int i    = base + ii;
        int pp   = i >> 7;
        int rem  = i & 127;
        int half = rem >> 6;
        int w    = rem & 63;
        int tx   = w >> 2;
        int q    = w & 3;
        int k    = 4 * tx + 2 * half + (q >> 1);
        int e    = q & 1;
        int p    = 2 * pp + e;
        float v = 0.f;
        if (k < KK) v = C[k * PD + p] * inv[k];
        g_chat2[i] = v;
    }
}

// ============================================================
// K1: gathered cosine-score GEMM.
// Block: 64 rows x 64 k, 256 threads, 4x4 tile/thread.
// Staging via cp.async.bulk (UBLKCP): 64 x 1200B row gathers +
// 8 x 9600B chat chunks through ONE mbarrier -> ~72 issue slots
// instead of 9600 LDGSTS (rt=8) that dominated the old prologue.
// Mainloop: software-pipelined fp32x2 register double-buffer.
// ============================================================
__global__ void __launch_bounds__(256, 1)
k1_scores(const int* __restrict__ idx, const float* __restrict__ emb) {
    extern __shared__ float sm1[];
    float* ch = sm1;                 // CH_ELEMS floats
    float* xs = sm1 + CH_ELEMS;      // BM * XSS floats
    __shared__ float inv[BM];
    __shared__ __align__(8) unsigned long long s_mbar;

    const int tid  = threadIdx.x;
    const int lane = tid & 31;
    const int warp = tid >> 5;
    const int row0 = blockIdx.x * BM;
    const unsigned mbar = s2u(&s_mbar);

    if (tid == 0)
        asm volatile("mbarrier.init.shared.b64 [%0], %1;"
                     :: "r"(mbar), "r"(1u) : "memory");
    __syncthreads();
    if (tid == 0)
        asm volatile("mbarrier.arrive.expect_tx.shared.b64 _, [%0], %1;"
                     :: "r"(mbar), "r"((unsigned)TOTAL_TX) : "memory");
    __syncthreads();

    // issue bulk copies: gather rows (tid<64) + chat chunks (tid 64..71)
    if (tid < BM) {
        const char* src = (const char*)(emb + (size_t)idx[row0 + tid] * PD);
        bulk_cp(s2u(xs + tid * XSS), src, ROW_BYTES, mbar);
    } else if (tid < BM + 8) {
        const int c = tid - BM;
        bulk_cp(s2u(ch) + (unsigned)c * (CH_BYTES / 8),
                (const char*)g_chat2 + c * (CH_BYTES / 8),
                CH_BYTES / 8, mbar);
    }
    mbar_wait(mbar, 0);
    __syncthreads();

    // inverse norms (warp per row)
    for (int r = warp; r < BM; r += 8) {
        const float* xr = xs + r * XSS;
        float ss = 0.f;
        #pragma unroll
        for (int i = 0; i < 10; i++) {
            int p = lane + 32 * i;
            if (p < PD) { float v = xr[p]; ss = fmaf(v, v, ss); }
        }
        #pragma unroll
        for (int o = 16; o; o >>= 1) ss += __shfl_xor_sync(0xffffffffu, ss, o);
        if (lane == 0) inv[r] = 1.f / (sqrtf(ss) + 0.001f);
    }
    __syncthreads();

    const int tx = tid & 15;   // k direction (4 k each)
    const int ty = tid >> 4;   // row direction (4 rows each)

    unsigned long long acc[4][4];
    #pragma unroll
    for (int i = 0; i < 4; i++)
        #pragma unroll
        for (int j = 0; j < 4; j++) acc[i][j] = 0ull;

    const float* aBase = xs + (ty * 4) * XSS;
    const float* bBase = ch + tx * 4;   // 16B-stride chunks, conflict-free

    // ---- software-pipelined mainloop: 2 p-pairs per iteration ----
    F4U2 aC[4], aN[4];
    ulonglong2 bC[4], bN[4];

    #pragma unroll
    for (int i = 0; i < 4; i++)
        aC[i].f = *(const float4*)(aBase + i * XSS);
    bC[0] = *(const ulonglong2*)(bBase);
    bC[1] = *(const ulonglong2*)(bBase + 64);
    bC[2] = *(const ulonglong2*)(bBase + 128);
    bC[3] = *(const ulonglong2*)(bBase + 192);

    #pragma unroll 1
    for (int pp = 0; pp < 148; pp += 2) {
        const float* aP = aBase + 2 * (pp + 2);
        const float* bP = bBase + (pp + 2) * 128;
        #pragma unroll
        for (int i = 0; i < 4; i++)
            aN[i].f = *(const float4*)(aP + i * XSS);
        bN[0] = *(const ulonglong2*)(bP);
        bN[1] = *(const ulonglong2*)(bP + 64);
        bN[2] = *(const ulonglong2*)(bP + 128);
        bN[3] = *(const ulonglong2*)(bP + 192);
        #pragma unroll
        for (int i = 0; i < 4; i++) {
            fma2(acc[i][0], aC[i].u[0], bC[0].x);
            fma2(acc[i][1], aC[i].u[0], bC[0].y);
            fma2(acc[i][2], aC[i].u[0], bC[1].x);
            fma2(acc[i][3], aC[i].u[0], bC[1].y);
        }
        #pragma unroll
        for (int i = 0; i < 4; i++) {
            fma2(acc[i][0], aC[i].u[1], bC[2].x);
            fma2(acc[i][1], aC[i].u[1], bC[2].y);
            fma2(acc[i][2], aC[i].u[1], bC[3].x);
            fma2(acc[i][3], aC[i].u[1], bC[3].y);
        }
        #pragma unroll
        for (int i = 0; i < 4; i++) aC[i] = aN[i];
        #pragma unroll
        for (int i = 0; i < 4; i++) bC[i] = bN[i];
    }
    #pragma unroll
    for (int i = 0; i < 4; i++) {
        fma2(acc[i][0], aC[i].u[0], bC[0].x);
        fma2(acc[i][1], aC[i].u[0], bC[0].y);
        fma2(acc[i][2], aC[i].u[0], bC[1].x);
        fma2(acc[i][3], aC[i].u[0], bC[1].y);
    }
    #pragma unroll
    for (int i = 0; i < 4; i++) {
        fma2(acc[i][0], aC[i].u[1], bC[2].x);
        fma2(acc[i][1], aC[i].u[1], bC[2].y);
        fma2(acc[i][2], aC[i].u[1], bC[3].x);
        fma2(acc[i][3], aC[i].u[1], bC[3].y);
    }

    // epilogue: scale by 1/(||x||+eps), store k<50
    #pragma unroll
    for (int i = 0; i < 4; i++) {
        int row = row0 + ty * 4 + i;
        float iv = inv[ty * 4 + i];
        float* gout = g_G + (size_t)row * KK;
        #pragma unroll
        for (int j = 0; j < 4; j++) {
            int k = tx * 4 + j;
            if (k < KK) gout[k] = sum2(acc[i][j]) * iv;
        }
    }
}

// ============================================================
// K2: per-batch conv(11) + relu + max-over-k + softmax over s.
// One block per b, 512 threads. Padded smem tile, stride 51.
// ============================================================
#define GST 51
#define GROWS (SS + 2*RR)   // 522

__global__ void __launch_bounds__(512, 1)
k2_attn(const float* __restrict__ cw, const float* __restrict__ cbp) {
    extern __shared__ float Gs[];   // GROWS * GST
    __shared__ float red1[16], red2[16];
    __shared__ float wloc[11];
    __shared__ float sc[3];         // [0]=conv_b, [1]=max, [2]=sum

    const int b = blockIdx.x, tid = threadIdx.x;
    if (tid < 11) wloc[tid] = cw[tid];
    if (tid == 16) sc[0] = cbp[0];

    for (int i = tid; i < RR * GST; i += 512) {
        Gs[i] = 0.f;
        Gs[(SS + RR) * GST + i] = 0.f;
    }
    const float* Gb = g_G + (size_t)b * SS * KK;
    for (int i = tid; i < SS * KK; i += 512) {
        int s = i / KK, k = i - s * KK;
        Gs[(s + RR) * GST + k] = Gb[i];
    }
    __syncthreads();

    const int s = tid;
    const float cbv = sc[0];
    float m = 0.f;   // relu >= 0
    for (int k = 0; k < KK; k++) {
        float v = cbv;
        const float* gp = Gs + s * GST + k;
        #pragma unroll
        for (int j = 0; j < 11; j++) v = fmaf(wloc[j], gp[j * GST], v);
        m = fmaxf(m, fmaxf(v, 0.f));
    }

    const int lane = tid & 31, warp = tid >> 5;
    float mx = m;
    #pragma unroll
    for (int o = 16; o; o >>= 1) mx = fmaxf(mx, __shfl_xor_sync(0xffffffffu, mx, o));
    if (lane == 0) red1[warp] = mx;
    __syncthreads();
    if (warp == 0) {
        float v = (lane < 16) ? red1[lane] : -1e30f;
        #pragma unroll
        for (int o = 8; o; o >>= 1) v = fmaxf(v, __shfl_xor_sync(0xffffffffu, v, o));
        if (lane == 0) sc[1] = v;
    }
    __syncthreads();
    float e = expf(m - sc[1]);
    float sum = e;
    #pragma unroll
    for (int o = 16; o; o >>= 1) sum += __shfl_xor_sync(0xffffffffu, sum, o);
    if (lane == 0) red2[warp] = sum;
    __syncthreads();
    if (warp == 0) {
        float v = (lane < 16) ? red2[lane] : 0.f;
        #pragma unroll
        for (int o = 8; o; o >>= 1) v += __shfl_xor_sync(0xffffffffu, v, o);
        if (lane == 0) sc[2] = v;
    }
    __syncthreads();
    g_beta[b * SS + s] = e / sc[2];
}

// ============================================================
// K3a: pooling partials. grid (8 chunks, 64 b), 320 threads,
// 64 s per block (measured-best config).
// ============================================================
__global__ void __launch_bounds__(320, 1)
k3a_pool(const int* __restrict__ idx, const float* __restrict__ emb) {
    __shared__ float sbeta[64];
    __shared__ int   sidx[64];
    const int cx = blockIdx.x, b = blockIdx.y, tid = threadIdx.x;
    const int s0 = b * SS + cx * 64;
    if (tid < 64) {
        sbeta[tid] = g_beta[s0 + tid];
        sidx[tid]  = idx[s0 + tid];
    }
    __syncthreads();
    if (tid < PD) {
        float a0 = 0.f, a1 = 0.f, a2 = 0.f, a3 = 0.f;
        #pragma unroll 4
        for (int s = 0; s < 64; s += 4) {
            a0 = fmaf(sbeta[s],     emb[(size_t)sidx[s]     * PD + tid], a0);
            a1 = fmaf(sbeta[s + 1], emb[(size_t)sidx[s + 1] * PD + tid], a1);
            a2 = fmaf(sbeta[s + 2], emb[(size_t)sidx[s + 2] * PD + tid], a2);
            a3 = fmaf(sbeta[s + 3], emb[(size_t)sidx[s + 3] * PD + tid], a3);
        }
        g_part[(b * NCH + cx) * PD + tid] = (a0 + a1) + (a2 + a3);
    }
}

// ============================================================
// K3b: combine partials + final GEMV out = pooled @ W2^T + b2.
// ============================================================
__global__ void __launch_bounds__(320, 4)
k3b_out(const float* __restrict__ W2, const float* __restrict__ b2,
        float* __restrict__ out) {
    __shared__ float pooled[PD];
    const int b = blockIdx.x, tid = threadIdx.x;
    if (tid < PD) {
        float s = 0.f;
        #pragma unroll
        for (int c = 0; c < NCH; c++) s += g_part[(b * NCH + c) * PD + tid];
        pooled[tid] = s * (1.0f / (float)SS);
    }
    __syncthreads();

    const int warp = tid >> 5, lane = tid & 31;  // 10 warps x 5 k
    #pragma unroll
    for (int kk = 0; kk < 5; kk++) {
        int k = warp * 5 + kk;
        float d = 0.f;
        for (int p = lane; p < PD; p += 32) d = fmaf(pooled[p], W2[k * PD + p], d);
        #pragma unroll
        for (int o = 16; o; o >>= 1) d += __shfl_xor_sync(0xffffffffu, d, o);
        if (lane == 0) out[b * KK + k] = d + b2[k];
    }
}

// ============================================================
extern "C" void kernel_launch(void* const* d_in, const int* in_sizes, int n_in,
                              void* d_out, int out_size) {
    const int*   idx    = (const int*)d_in[0];
    const float* emb    = (const float*)d_in[1];
    const float* C      = (const float*)d_in[2];
    const float* conv_w = (const float*)d_in[3];
    const float* conv_b = (const float*)d_in[4];
    const float* W2     = (const float*)d_in[5];
    const float* b2     = (const float*)d_in[6];
    float*       out    = (float*)d_out;

    const int sm1 = (CH_ELEMS + BM * XSS) * (int)sizeof(float);   // ~153 KB
    const int sm2 = GROWS * GST * (int)sizeof(float);             // ~106 KB
    cudaFuncSetAttribute(k1_scores, cudaFuncAttributeMaxDynamicSharedMemorySize, sm1);
    cudaFuncSetAttribute(k2_attn,   cudaFuncAttributeMaxDynamicSharedMemorySize, sm2);

    k0_chat<<<4, 256>>>(C);
    k1_scores<<<NROWS / BM, 256, sm1>>>(idx, emb);
    k2_attn<<<BB, 512, sm2>>>(conv_w, conv_b);
    k3a_pool<<<dim3(NCH, BB), 320>>>(idx, emb);
    k3b_out<<<BB, 320>>>(W2, b2, out);
}